// round 1
// baseline (speedup 1.0000x reference)
#include <cuda_runtime.h>

// IndRNN: out[b,t,r] = relu(xp[b,t,r] + u[r]*h_prev), xp = x@W + bias, h0 = 1
// Kernel 1: fp32 SGEMM (M=65536, N=512, K=512) + bias -> writes xp into d_out
// Kernel 2: in-place per-(b,r) scan over t with software-pipelined loads

#define BM 128
#define BN 64
#define BK 16
#define TM 8
#define TN 4

__global__ __launch_bounds__(256) void indrnn_gemm_bias(
    const float* __restrict__ A,     // [65536, 512]
    const float* __restrict__ W,     // [512, 512]
    const float* __restrict__ bias,  // [512]
    float* __restrict__ C)           // [65536, 512]
{
    const int K = 512;
    const int N = 512;

    __shared__ float As[BK][BM];   // [k][m]
    __shared__ float Ws[BK][BN];   // [k][n]

    const int bm = blockIdx.y * BM;
    const int bn = blockIdx.x * BN;
    const int tid = (int)threadIdx.x;

    const int ty = tid >> 4;   // 0..15 -> 8 m-rows each
    const int tx = tid & 15;   // 0..15 -> 4 n-cols each

    // global load mapping
    const int arow = tid >> 2;   // 0..63 (two rows per thread: arow, arow+64)
    const int ak4  = tid & 3;    // float4 index along K within BK
    const int wrow = tid >> 4;   // 0..15 (k within tile)
    const int wc4  = tid & 15;   // float4 index along N within BN

    float acc[TM][TN];
    #pragma unroll
    for (int i = 0; i < TM; i++)
        #pragma unroll
        for (int j = 0; j < TN; j++)
            acc[i][j] = 0.0f;

    const float* Aptr0 = A + (size_t)(bm + arow) * K + ak4 * 4;
    const float* Aptr1 = Aptr0 + (size_t)64 * K;
    const float* Wptr  = W + (size_t)wrow * N + bn + wc4 * 4;

    for (int k0 = 0; k0 < K; k0 += BK) {
        float4 a0 = *(const float4*)(Aptr0 + k0);
        float4 a1 = *(const float4*)(Aptr1 + k0);
        float4 w0 = *(const float4*)(Wptr + (size_t)k0 * N);

        __syncthreads();  // protect previous tile's reads before overwrite

        const int kb = ak4 * 4;
        As[kb + 0][arow] = a0.x;
        As[kb + 1][arow] = a0.y;
        As[kb + 2][arow] = a0.z;
        As[kb + 3][arow] = a0.w;
        As[kb + 0][arow + 64] = a1.x;
        As[kb + 1][arow + 64] = a1.y;
        As[kb + 2][arow + 64] = a1.z;
        As[kb + 3][arow + 64] = a1.w;
        *(float4*)&Ws[wrow][wc4 * 4] = w0;

        __syncthreads();

        #pragma unroll
        for (int kk = 0; kk < BK; kk++) {
            float4 ra0 = *(const float4*)&As[kk][ty * TM];
            float4 ra1 = *(const float4*)&As[kk][ty * TM + 4];
            float4 rb  = *(const float4*)&Ws[kk][tx * TN];
            float a[TM] = {ra0.x, ra0.y, ra0.z, ra0.w, ra1.x, ra1.y, ra1.z, ra1.w};
            float bv[TN] = {rb.x, rb.y, rb.z, rb.w};
            #pragma unroll
            for (int i = 0; i < TM; i++)
                #pragma unroll
                for (int j = 0; j < TN; j++)
                    acc[i][j] = fmaf(a[i], bv[j], acc[i][j]);
        }
    }

    // epilogue: add bias, store
    float4 bb = *(const float4*)&bias[bn + tx * TN];
    #pragma unroll
    for (int i = 0; i < TM; i++) {
        float4 o;
        o.x = acc[i][0] + bb.x;
        o.y = acc[i][1] + bb.y;
        o.z = acc[i][2] + bb.z;
        o.w = acc[i][3] + bb.w;
        *(float4*)&C[(size_t)(bm + ty * TM + i) * N + bn + tx * TN] = o;
    }
}

// One thread per (b, r). Loads for step t don't depend on h, so batch 16
// loads ahead of the serial FMA/relu chain -> MLP=16 per thread.
__global__ __launch_bounds__(256) void indrnn_scan(
    float* __restrict__ xp,         // [64, 1024, 512], in-place
    const float* __restrict__ u)    // [512]
{
    const int T = 1024;
    const int R = 512;
    int idx = blockIdx.x * blockDim.x + threadIdx.x;  // 0..32767
    int b = idx >> 9;
    int r = idx & 511;

    float uu = u[r];
    float h = 1.0f;
    float* p = xp + (size_t)b * T * R + r;

    #pragma unroll 1
    for (int t0 = 0; t0 < T; t0 += 16) {
        float v[16];
        #pragma unroll
        for (int j = 0; j < 16; j++)
            v[j] = p[(t0 + j) * R];
        #pragma unroll
        for (int j = 0; j < 16; j++) {
            h = fmaxf(fmaf(uu, h, v[j]), 0.0f);
            v[j] = h;
        }
        #pragma unroll
        for (int j = 0; j < 16; j++)
            p[(t0 + j) * R] = v[j];
    }
}

extern "C" void kernel_launch(void* const* d_in, const int* in_sizes, int n_in,
                              void* d_out, int out_size)
{
    const float* x  = (const float*)d_in[0];  // [64,1024,512]
    const float* W  = (const float*)d_in[1];  // [512,512]
    const float* u  = (const float*)d_in[2];  // [512]
    const float* b  = (const float*)d_in[3];  // [512]
    float* out = (float*)d_out;               // [64,1024,512]

    (void)in_sizes; (void)n_in; (void)out_size;

    // GEMM: M = 64*1024 = 65536 rows
    dim3 ggrid(512 / BN, 65536 / BM);  // (8, 512)
    indrnn_gemm_bias<<<ggrid, 256>>>(x, W, b, out);

    // Scan: 64*512 = 32768 threads
    indrnn_scan<<<128, 256>>>(out, u);
}

// round 2
// speedup vs baseline: 1.0525x; 1.0525x over previous
#include <cuda_runtime.h>

// IndRNN: out[b,t,r] = relu(xp[b,t,r] + u[r]*h_prev), xp = x@W + bias, h0 = 1
// Kernel 1: fp32 SGEMM (M=65536, N=512, K=512) + bias -> writes xp into d_out
// Kernel 2: in-place per-(b,r) scan over t with software-pipelined loads

#define BM 128
#define BN 64
#define BK 16
#define TM 8
#define TN 4

__global__ __launch_bounds__(256) void indrnn_gemm_bias(
    const float* __restrict__ A,     // [65536, 512]
    const float* __restrict__ W,     // [512, 512]
    const float* __restrict__ bias,  // [512]
    float* __restrict__ C)           // [65536, 512]
{
    const int K = 512;
    const int N = 512;

    __shared__ float As[BK][BM];   // [k][m]
    __shared__ float Ws[BK][BN];   // [k][n]

    const int bm = blockIdx.y * BM;
    const int bn = blockIdx.x * BN;
    const int tid = (int)threadIdx.x;

    const int ty = tid >> 4;   // 0..15 -> 8 m-rows each
    const int tx = tid & 15;   // 0..15 -> 4 n-cols each

    // global load mapping
    const int arow = tid >> 2;   // 0..63 (two rows per thread: arow, arow+64)
    const int ak4  = tid & 3;    // float4 index along K within BK
    const int wrow = tid >> 4;   // 0..15 (k within tile)
    const int wc4  = tid & 15;   // float4 index along N within BN

    float acc[TM][TN];
    #pragma unroll
    for (int i = 0; i < TM; i++)
        #pragma unroll
        for (int j = 0; j < TN; j++)
            acc[i][j] = 0.0f;

    const float* Aptr0 = A + (size_t)(bm + arow) * K + ak4 * 4;
    const float* Aptr1 = Aptr0 + (size_t)64 * K;
    const float* Wptr  = W + (size_t)wrow * N + bn + wc4 * 4;

    for (int k0 = 0; k0 < K; k0 += BK) {
        float4 a0 = *(const float4*)(Aptr0 + k0);
        float4 a1 = *(const float4*)(Aptr1 + k0);
        float4 w0 = *(const float4*)(Wptr + (size_t)k0 * N);

        __syncthreads();  // protect previous tile's reads before overwrite

        const int kb = ak4 * 4;
        As[kb + 0][arow] = a0.x;
        As[kb + 1][arow] = a0.y;
        As[kb + 2][arow] = a0.z;
        As[kb + 3][arow] = a0.w;
        As[kb + 0][arow + 64] = a1.x;
        As[kb + 1][arow + 64] = a1.y;
        As[kb + 2][arow + 64] = a1.z;
        As[kb + 3][arow + 64] = a1.w;
        *(float4*)&Ws[wrow][wc4 * 4] = w0;

        __syncthreads();

        #pragma unroll
        for (int kk = 0; kk < BK; kk++) {
            float4 ra0 = *(const float4*)&As[kk][ty * TM];
            float4 ra1 = *(const float4*)&As[kk][ty * TM + 4];
            float4 rb  = *(const float4*)&Ws[kk][tx * TN];
            float a[TM] = {ra0.x, ra0.y, ra0.z, ra0.w, ra1.x, ra1.y, ra1.z, ra1.w};
            float bv[TN] = {rb.x, rb.y, rb.z, rb.w};
            #pragma unroll
            for (int i = 0; i < TM; i++)
                #pragma unroll
                for (int j = 0; j < TN; j++)
                    acc[i][j] = fmaf(a[i], bv[j], acc[i][j]);
        }
    }

    // epilogue: add bias, store
    float4 bb = *(const float4*)&bias[bn + tx * TN];
    #pragma unroll
    for (int i = 0; i < TM; i++) {
        float4 o;
        o.x = acc[i][0] + bb.x;
        o.y = acc[i][1] + bb.y;
        o.z = acc[i][2] + bb.z;
        o.w = acc[i][3] + bb.w;
        *(float4*)&C[(size_t)(bm + ty * TM + i) * N + bn + tx * TN] = o;
    }
}

// One thread per (b, r). Loads for step t don't depend on h, so batch 16
// loads ahead of the serial FMA/relu chain -> MLP=16 per thread.
__global__ __launch_bounds__(256) void indrnn_scan(
    float* __restrict__ xp,         // [64, 1024, 512], in-place
    const float* __restrict__ u)    // [512]
{
    const int T = 1024;
    const int R = 512;
    int idx = blockIdx.x * blockDim.x + threadIdx.x;  // 0..32767
    int b = idx >> 9;
    int r = idx & 511;

    float uu = u[r];
    float h = 1.0f;
    float* p = xp + (size_t)b * T * R + r;

    #pragma unroll 1
    for (int t0 = 0; t0 < T; t0 += 16) {
        float v[16];
        #pragma unroll
        for (int j = 0; j < 16; j++)
            v[j] = p[(t0 + j) * R];
        #pragma unroll
        for (int j = 0; j < 16; j++) {
            h = fmaxf(fmaf(uu, h, v[j]), 0.0f);
            v[j] = h;
        }
        #pragma unroll
        for (int j = 0; j < 16; j++)
            p[(t0 + j) * R] = v[j];
    }
}

extern "C" void kernel_launch(void* const* d_in, const int* in_sizes, int n_in,
                              void* d_out, int out_size)
{
    const float* x  = (const float*)d_in[0];  // [64,1024,512]
    const float* W  = (const float*)d_in[1];  // [512,512]
    const float* u  = (const float*)d_in[2];  // [512]
    const float* b  = (const float*)d_in[3];  // [512]
    float* out = (float*)d_out;               // [64,1024,512]

    (void)in_sizes; (void)n_in; (void)out_size;

    // GEMM: M = 64*1024 = 65536 rows
    dim3 ggrid(512 / BN, 65536 / BM);  // (8, 512)
    indrnn_gemm_bias<<<ggrid, 256>>>(x, W, b, out);

    // Scan: 64*512 = 32768 threads
    indrnn_scan<<<128, 256>>>(out, u);
}